// round 7
// baseline (speedup 1.0000x reference)
#include <cuda_runtime.h>
#include <cuda_bf16.h>
#include <math.h>

// CBOW negative-sampling loss, fused single-kernel version.
// Inputs (metadata order):
//   d_in[0] i_emb        float32 [200001, 50]
//   d_in[1] o_emb        float32 [200001, 50]
//   d_in[2] target_wids  int32   [B]
//   d_in[3] context_wids int32   [B, 10]
//   d_in[4] neg_wids     int32   [B, 10]
// Output: scalar float32 = -(sum log_sigmoid(pos) + sum log_sigmoid(-neg))
//
// One warp per batch element; lanes 0..24 each hold one float2 of a row.
// ALL 21 row loads are issued before any math (MLP ~21 per lane): the
// round-5 profile showed a latency-bound kernel pinned at regs=32 with no
// saturated pipe. We deliberately spend ~90 regs to buy full MLP. Loads are
// written as predicated stores into pre-zeroed registers so ptxas emits
// @P LDG.64 without SEL chains.

#define DIM   50
#define CTX   10
#define NNEG  10
#define WPB   8            // warps (batch elements) per block
#define TPB   (WPB * 32)
#define MAX_BLOCKS 4096

__device__ float g_partials[MAX_BLOCKS];
__device__ unsigned int g_count = 0;

__global__ void __launch_bounds__(TPB)
cbow_loss_kernel(const float* __restrict__ i_emb,
                 const float* __restrict__ o_emb,
                 const int*   __restrict__ tgt_w,
                 const int*   __restrict__ ctx_w,
                 const int*   __restrict__ neg_w,
                 float*       __restrict__ out,
                 int B, int nblk)
{
    const int warp = threadIdx.x >> 5;
    const int lane = threadIdx.x & 31;
    const int b    = blockIdx.x * WPB + warp;

    float warp_loss = 0.0f;

    if (b < B) {
        // Warp-uniform index loads, int2-vectorized (row base 40B -> 8B aligned).
        const int2* __restrict__ cp = (const int2*)(ctx_w + (size_t)b * CTX);
        const int2* __restrict__ np = (const int2*)(neg_w + (size_t)b * NNEG);
        int cidx[CTX], nidx[NNEG];
        #pragma unroll
        for (int j = 0; j < CTX / 2; ++j) {
            int2 c = __ldg(cp + j);
            cidx[2 * j] = c.x; cidx[2 * j + 1] = c.y;
            int2 q = __ldg(np + j);
            nidx[2 * j] = q.x; nidx[2 * j + 1] = q.y;
        }
        const int t = __ldg(tgt_w + b);

        const bool act = (lane < DIM / 2);       // lanes 0..24 carry row data

        // ---- Issue ALL 21 row loads up front (independent -> MLP ~21) ----
        float2 cv[CTX], nv[NNEG], tv;
        #pragma unroll
        for (int j = 0; j < CTX; ++j) cv[j] = make_float2(0.0f, 0.0f);
        #pragma unroll
        for (int n = 0; n < NNEG; ++n) nv[n] = make_float2(0.0f, 0.0f);
        tv = make_float2(0.0f, 0.0f);

        if (act) {
            #pragma unroll
            for (int j = 0; j < CTX; ++j)
                cv[j] = __ldg((const float2*)(i_emb + (size_t)cidx[j] * DIM) + lane);
            tv = __ldg((const float2*)(o_emb + (size_t)t * DIM) + lane);
            #pragma unroll
            for (int n = 0; n < NNEG; ++n)
                nv[n] = __ldg((const float2*)(o_emb + (size_t)nidx[n] * DIM) + lane);
        }

        // ---- Math phase ----
        // Context sum (mean folded into score scale below). Two chains for ILP.
        float a0 = cv[0].x, a1 = cv[0].y;
        float b0 = cv[1].x, b1 = cv[1].y;
        #pragma unroll
        for (int j = 2; j < CTX; j += 2) {
            a0 += cv[j].x;     a1 += cv[j].y;
            b0 += cv[j + 1].x; b1 += cv[j + 1].y;
        }
        a0 += b0; a1 += b1;

        float pos = a0 * tv.x + a1 * tv.y;
        float negp[NNEG];
        #pragma unroll
        for (int n = 0; n < NNEG; ++n)
            negp[n] = a0 * nv[n].x + a1 * nv[n].y;

        // Butterfly reduce all 11 dot products across the warp.
        #pragma unroll
        for (int off = 16; off > 0; off >>= 1) {
            pos += __shfl_xor_sync(0xffffffffu, pos, off);
            #pragma unroll
            for (int n = 0; n < NNEG; ++n)
                negp[n] += __shfl_xor_sync(0xffffffffu, negp[n], off);
        }

        // Distribute: lane 0 -> pos, lane n+1 -> negp[n]; lanes 11..31 dummy.
        float x = pos;
        #pragma unroll
        for (int n = 0; n < NNEG; ++n)
            x = (lane == n + 1) ? negp[n] : x;

        // arg = +pos/CTX on lane 0, -neg/CTX on lanes 1..10 (mean folded in).
        const float inv_ctx = 1.0f / (float)CTX;
        const float scale = (lane == 0) ? inv_ctx : -inv_ctx;
        const float arg   = x * scale;

        // log_sigmoid issued ONCE per warp: min(a,0) - log(1 + exp(-|a|)).
        float ls = fminf(arg, 0.0f) - __logf(1.0f + __expf(-fabsf(arg)));
        ls = (lane <= NNEG) ? ls : 0.0f;         // zero dummy lanes

        // Warp-sum the per-lane losses.
        #pragma unroll
        for (int off = 16; off > 0; off >>= 1)
            ls += __shfl_xor_sync(0xffffffffu, ls, off);
        warp_loss = ls;                          // identical on all lanes
    }

    // Block reduce: one value per warp.
    __shared__ float s_warp[WPB];
    if (lane == 0) s_warp[warp] = warp_loss;
    __syncthreads();

    __shared__ bool s_last;
    if (threadIdx.x == 0) {
        float s = 0.0f;
        #pragma unroll
        for (int w = 0; w < WPB; ++w) s += s_warp[w];
        g_partials[blockIdx.x] = s;
        __threadfence();
        unsigned int prev = atomicAdd(&g_count, 1u);
        s_last = (prev == (unsigned int)(nblk - 1));
    }
    __syncthreads();

    // Last block reduces all per-block partials (fixed order -> deterministic)
    // and writes the final loss; resets the counter for graph replay.
    if (s_last) {
        if (threadIdx.x < 32) {
            float acc = 0.0f;
            for (int i = threadIdx.x; i < nblk; i += 32)
                acc += g_partials[i];
            #pragma unroll
            for (int off = 16; off > 0; off >>= 1)
                acc += __shfl_xor_sync(0xffffffffu, acc, off);
            if (threadIdx.x == 0) {
                out[0] = -acc;
                g_count = 0;          // reset for next graph replay
            }
        }
    }
}

extern "C" void kernel_launch(void* const* d_in, const int* in_sizes, int n_in,
                              void* d_out, int out_size)
{
    const float* i_emb = (const float*)d_in[0];
    const float* o_emb = (const float*)d_in[1];
    const int*   tgt   = (const int*)d_in[2];
    const int*   ctx   = (const int*)d_in[3];
    const int*   neg   = (const int*)d_in[4];
    float*       out   = (float*)d_out;

    const int B = in_sizes[2];
    const int nblk = (B + WPB - 1) / WPB;   // 2048 for B=16384

    cbow_loss_kernel<<<nblk, TPB>>>(i_emb, o_emb, tgt, ctx, neg, out, B, nblk);
}

// round 8
// speedup vs baseline: 1.0035x; 1.0035x over previous
#include <cuda_runtime.h>
#include <cuda_bf16.h>
#include <math.h>

// CBOW negative-sampling loss, fused single-kernel version.
// Inputs (metadata order):
//   d_in[0] i_emb        float32 [200001, 50]
//   d_in[1] o_emb        float32 [200001, 50]
//   d_in[2] target_wids  int32   [B]
//   d_in[3] context_wids int32   [B, 10]
//   d_in[4] neg_wids     int32   [B, 10]
// Output: scalar float32 = -(sum log_sigmoid(pos) + sum log_sigmoid(-neg))
//
// One warp per batch element; lanes 0..24 each hold one float2 of a row.
// Round-7 lesson: ptxas sinks C++-level "front-batched" loads back to
// consumption order (regs stayed 44 -> MLP ~6). This version forces all 21
// row loads in flight with asm volatile ld.global.nc.v2.f32 (cannot be
// reordered or sunk), spending ~95 regs to buy true MLP=21. Inactive lanes
// load a clamped in-bounds address and are zeroed via one mask multiply.

#define DIM   50
#define CTX   10
#define NNEG  10
#define WPB   8            // warps (batch elements) per block
#define TPB   (WPB * 32)
#define MAX_BLOCKS 4096

__device__ float g_partials[MAX_BLOCKS];
__device__ unsigned int g_count = 0;

// Non-sinkable vector load: asm volatile pins program order and liveness.
__device__ __forceinline__ float2 ldg_f2_pinned(const float2* p) {
    float2 v;
    asm volatile("ld.global.nc.v2.f32 {%0, %1}, [%2];"
                 : "=f"(v.x), "=f"(v.y) : "l"(p));
    return v;
}

__global__ void __launch_bounds__(TPB)
cbow_loss_kernel(const float* __restrict__ i_emb,
                 const float* __restrict__ o_emb,
                 const int*   __restrict__ tgt_w,
                 const int*   __restrict__ ctx_w,
                 const int*   __restrict__ neg_w,
                 float*       __restrict__ out,
                 int B, int nblk)
{
    const int warp = threadIdx.x >> 5;
    const int lane = threadIdx.x & 31;
    const int b    = blockIdx.x * WPB + warp;

    float warp_loss = 0.0f;

    if (b < B) {
        // Warp-uniform index loads, int2-vectorized (row base 40B -> 8B aligned).
        const int2* __restrict__ cp = (const int2*)(ctx_w + (size_t)b * CTX);
        const int2* __restrict__ np = (const int2*)(neg_w + (size_t)b * NNEG);
        int cidx[CTX], nidx[NNEG];
        #pragma unroll
        for (int j = 0; j < CTX / 2; ++j) {
            int2 c = __ldg(cp + j);
            cidx[2 * j] = c.x; cidx[2 * j + 1] = c.y;
            int2 q = __ldg(np + j);
            nidx[2 * j] = q.x; nidx[2 * j + 1] = q.y;
        }
        const int t = __ldg(tgt_w + b);

        const bool act = (lane < DIM / 2);       // lanes 0..24 carry row data
        const int  lx  = act ? lane : 0;         // clamp: inactive lanes read col 0 (in-bounds)
        const float mask = act ? 1.0f : 0.0f;

        // ---- 21 pinned loads, back-to-back: true MLP = 21 ----
        float2 cv[CTX], nv[NNEG], tv;
        #pragma unroll
        for (int j = 0; j < CTX; ++j)
            cv[j] = ldg_f2_pinned((const float2*)(i_emb + (size_t)cidx[j] * DIM) + lx);
        tv = ldg_f2_pinned((const float2*)(o_emb + (size_t)t * DIM) + lx);
        #pragma unroll
        for (int n = 0; n < NNEG; ++n)
            nv[n] = ldg_f2_pinned((const float2*)(o_emb + (size_t)nidx[n] * DIM) + lx);

        // ---- Math phase ----
        // Context sum (mean folded into score scale below). Two chains for ILP.
        float a0 = cv[0].x, a1 = cv[0].y;
        float b0 = cv[1].x, b1 = cv[1].y;
        #pragma unroll
        for (int j = 2; j < CTX; j += 2) {
            a0 += cv[j].x;     a1 += cv[j].y;
            b0 += cv[j + 1].x; b1 += cv[j + 1].y;
        }
        a0 += b0; a1 += b1;

        // Dot-product partials; mask zeroes the duplicated inactive lanes.
        float pos = (a0 * tv.x + a1 * tv.y) * mask;
        float negp[NNEG];
        #pragma unroll
        for (int n = 0; n < NNEG; ++n)
            negp[n] = (a0 * nv[n].x + a1 * nv[n].y) * mask;

        // Butterfly reduce all 11 dot products across the warp.
        #pragma unroll
        for (int off = 16; off > 0; off >>= 1) {
            pos += __shfl_xor_sync(0xffffffffu, pos, off);
            #pragma unroll
            for (int n = 0; n < NNEG; ++n)
                negp[n] += __shfl_xor_sync(0xffffffffu, negp[n], off);
        }

        // Distribute: lane 0 -> pos, lane n+1 -> negp[n]; lanes 11..31 dummy.
        float x = pos;
        #pragma unroll
        for (int n = 0; n < NNEG; ++n)
            x = (lane == n + 1) ? negp[n] : x;

        // arg = +pos/CTX on lane 0, -neg/CTX on lanes 1..10 (mean folded in).
        const float inv_ctx = 1.0f / (float)CTX;
        const float scale = (lane == 0) ? inv_ctx : -inv_ctx;
        const float arg   = x * scale;

        // log_sigmoid issued ONCE per warp: min(a,0) - log(1 + exp(-|a|)).
        float ls = fminf(arg, 0.0f) - __logf(1.0f + __expf(-fabsf(arg)));
        ls = (lane <= NNEG) ? ls : 0.0f;         // zero dummy lanes

        // Warp-sum the per-lane losses.
        #pragma unroll
        for (int off = 16; off > 0; off >>= 1)
            ls += __shfl_xor_sync(0xffffffffu, ls, off);
        warp_loss = ls;                          // identical on all lanes
    }

    // Block reduce: one value per warp.
    __shared__ float s_warp[WPB];
    if (lane == 0) s_warp[warp] = warp_loss;
    __syncthreads();

    __shared__ bool s_last;
    if (threadIdx.x == 0) {
        float s = 0.0f;
        #pragma unroll
        for (int w = 0; w < WPB; ++w) s += s_warp[w];
        g_partials[blockIdx.x] = s;
        __threadfence();
        unsigned int prev = atomicAdd(&g_count, 1u);
        s_last = (prev == (unsigned int)(nblk - 1));
    }
    __syncthreads();

    // Last block reduces all per-block partials (fixed order -> deterministic)
    // and writes the final loss; resets the counter for graph replay.
    if (s_last) {
        if (threadIdx.x < 32) {
            float acc = 0.0f;
            for (int i = threadIdx.x; i < nblk; i += 32)
                acc += g_partials[i];
            #pragma unroll
            for (int off = 16; off > 0; off >>= 1)
                acc += __shfl_xor_sync(0xffffffffu, acc, off);
            if (threadIdx.x == 0) {
                out[0] = -acc;
                g_count = 0;          // reset for next graph replay
            }
        }
    }
}

extern "C" void kernel_launch(void* const* d_in, const int* in_sizes, int n_in,
                              void* d_out, int out_size)
{
    const float* i_emb = (const float*)d_in[0];
    const float* o_emb = (const float*)d_in[1];
    const int*   tgt   = (const int*)d_in[2];
    const int*   ctx   = (const int*)d_in[3];
    const int*   neg   = (const int*)d_in[4];
    float*       out   = (float*)d_out;

    const int B = in_sizes[2];
    const int nblk = (B + WPB - 1) / WPB;   // 2048 for B=16384

    cbow_loss_kernel<<<nblk, TPB>>>(i_emb, o_emb, tgt, ctx, neg, out, B, nblk);
}